// round 14
// baseline (speedup 1.0000x reference)
#include <cuda_runtime.h>

#define DM 24
#define RD 10
#define NSEQ 512
#define ROWS 4096
#define APAD 12
#define NT 16          // 32-row tiles per batch
#define TS 32
#define NPAIRS 136     // NT*(NT+1)/2
#define CQS 52
#define ABP 14

typedef unsigned long long u64;

// Scratch (no runtime allocation allowed)
__device__ __align__(16) float g_A[ROWS * APAD];        // x@W1[0:24]+b1
__device__ __align__(16) float g_Bv[ROWS * APAD];       // x@W1[24:48]
__device__ __align__(16) float g_psum[NT][ROWS * RD];   // per-slot partial sums
__device__ __align__(16) float g_pmax[NT][ROWS * RD];   // per-slot partial maxes

// ---------------- f32x2 helpers ----------------
__device__ __forceinline__ u64 pk(float lo, float hi) {
    u64 r; asm("mov.b64 %0, {%1, %2};" : "=l"(r) : "f"(lo), "f"(hi)); return r;
}
__device__ __forceinline__ void upk(float& lo, float& hi, u64 v) {
    asm("mov.b64 {%0, %1}, %2;" : "=f"(lo), "=f"(hi) : "l"(v));
}
__device__ __forceinline__ u64 f2fma(u64 a, u64 b, u64 c) {
    u64 d; asm("fma.rn.f32x2 %0, %1, %2, %3;" : "=l"(d) : "l"(a), "l"(b), "l"(c)); return d;
}
__device__ __forceinline__ u64 f2add(u64 a, u64 b) {
    u64 d; asm("add.rn.f32x2 %0, %1, %2;" : "=l"(d) : "l"(a), "l"(b)); return d;
}
__device__ __forceinline__ void lds_v2u64(u64& a, u64& b, const float* p) {
    unsigned sa = (unsigned)__cvta_generic_to_shared((const void*)p);
    asm("ld.shared.v2.u64 {%0, %1}, [%2];" : "=l"(a), "=l"(b) : "r"(sa));
}
__device__ __forceinline__ u64 lds_u64(const float* p) {
    unsigned sa = (unsigned)__cvta_generic_to_shared((const void*)p);
    u64 a; asm("ld.shared.u64 %0, [%1];" : "=l"(a) : "r"(sa));
    return a;
}

// ---------------------------------------------------------------------------
// Kernel 1: per-row precompute
// ---------------------------------------------------------------------------
__global__ void precompute_kernel(const float* __restrict__ x,
                                  const float* __restrict__ W1,
                                  const float* __restrict__ b1) {
    int row = blockIdx.x * blockDim.x + threadIdx.x;
    if (row >= ROWS) return;
    float xv[DM];
    {
        const float4* x4 = (const float4*)(x + (size_t)row * DM);
#pragma unroll
        for (int k = 0; k < 6; k++) {
            float4 t = x4[k];
            xv[4*k] = t.x; xv[4*k+1] = t.y; xv[4*k+2] = t.z; xv[4*k+3] = t.w;
        }
    }
    float A[RD], Bv[RD];
#pragma unroll
    for (int r = 0; r < RD; r++) { A[r] = b1[r]; Bv[r] = 0.f; }
#pragma unroll
    for (int d = 0; d < DM; d++) {
        float xd = xv[d];
#pragma unroll
        for (int r = 0; r < RD; r++) {
            A[r]  = fmaf(xd, W1[d * RD + r], A[r]);
            Bv[r] = fmaf(xd, W1[(DM + d) * RD + r], Bv[r]);
        }
    }
#pragma unroll
    for (int r = 0; r < RD; r++) {
        g_A[row * APAD + r]  = A[r];
        g_Bv[row * APAD + r] = Bv[r];
    }
    g_A[row * APAD + 10] = 0.f;  g_A[row * APAD + 11] = 0.f;
    g_Bv[row * APAD + 10] = 0.f; g_Bv[row * APAD + 11] = 0.f;
}

// ---------------------------------------------------------------------------
// Kernel 2: symmetric tile-pair kernel. 1 warp per (batch, ti<=tj) tile pair.
// Lane l owns i = ibase+l (registers). Step s: j = jbase + ((l+s)&31) from
// warp-staged smem. S computed once; forward accumulated locally, backward
// shuffled to the j-owner lane. Diag tiles: s=1..15 both dirs + s=16 fwd only.
// ---------------------------------------------------------------------------
__global__ __launch_bounds__(128, 3)
void pair_kernel(const float* __restrict__ q,
                 const float* __restrict__ coord,
                 const float* __restrict__ W1,
                 const float* __restrict__ W2,
                 const float* __restrict__ b2) {
    __shared__ __align__(16) float s_cq[4][TS][CQS];  // j-tile coord/q (208B rows)
    __shared__ __align__(16) float s_aj[4][TS][ABP];  // A_j rows (56B stride)
    __shared__ __align__(16) float s_bj[4][TS][ABP];  // B_j rows (56B stride)
    __shared__ __align__(16) float s_w1[26][12];      // [d][r]; 24=qov, 25=dist
    __shared__ __align__(16) float s_w2[10][12];      // [rh][c]
    __shared__ __align__(16) float s_b2[12];

    const int tid = threadIdx.x;
    const int w = tid >> 5, lane = tid & 31;

    // --- block-wide weight staging ---
    for (int idx = tid; idx < 26 * 12; idx += 128) {
        int d = idx / 12, r = idx % 12;
        float v = 0.f;
        if (r < RD) {
            int row = (d < 24) ? (48 + d) : (d == 24 ? 72 : 73);
            v = W1[row * RD + r];
        }
        s_w1[d][r] = v;
    }
    for (int idx = tid; idx < 10 * 12; idx += 128) {
        int rh = idx / 12, c = idx % 12;
        s_w2[rh][c] = (c < RD) ? W2[rh * RD + c] : 0.f;
    }
    if (tid < 12) s_b2[tid] = (tid < RD) ? b2[tid] : 0.f;

    // --- unit -> (batch, ti, tj) ---
    const int unit = blockIdx.x * 4 + w;
    const int batch = unit / NPAIRS;
    int p = unit % NPAIRS;
    int ti = 0;
    while (p >= NT - ti) { p -= NT - ti; ti++; }
    const int tj = ti + p;
    const bool diag = (ti == tj);
    const int ibase = batch * NSEQ + ti * TS;
    const int jbase = batch * NSEQ + tj * TS;
    const int ri = ibase + lane;
    const int rj = jbase + lane;

    // --- stage j-tile (each lane stages its own row) ---
    {
        const float4* gc = (const float4*)(coord + (size_t)rj * DM);
        const float4* gq = (const float4*)(q + (size_t)rj * DM);
#pragma unroll
        for (int k = 0; k < 6; k++) {
            *(float4*)&s_cq[w][lane][4 * k]      = gc[k];
            *(float4*)&s_cq[w][lane][24 + 4 * k] = gq[k];
        }
        const float2* ga = (const float2*)(g_A + (size_t)rj * APAD);
        const float2* gb = (const float2*)(g_Bv + (size_t)rj * APAD);
#pragma unroll
        for (int k = 0; k < 5; k++) {
            *(float2*)&s_aj[w][lane][2 * k] = ga[k];
            *(float2*)&s_bj[w][lane][2 * k] = gb[k];
        }
    }
    // --- i-state in registers ---
    float ci[DM], qi[DM];
    {
        const float4* c4 = (const float4*)(coord + (size_t)ri * DM);
        const float4* q4 = (const float4*)(q + (size_t)ri * DM);
#pragma unroll
        for (int k = 0; k < 6; k++) {
            float4 t = c4[k]; ci[4*k]=t.x; ci[4*k+1]=t.y; ci[4*k+2]=t.z; ci[4*k+3]=t.w;
            float4 u = q4[k]; qi[4*k]=u.x; qi[4*k+1]=u.y; qi[4*k+2]=u.z; qi[4*k+3]=u.w;
        }
    }
    u64 Ai[5], Bi[5];
#pragma unroll
    for (int t = 0; t < 5; t++) {
        Ai[t] = *(const u64*)(g_A + (size_t)ri * APAD + 2 * t);
        Bi[t] = *(const u64*)(g_Bv + (size_t)ri * APAD + 2 * t);
    }

    __syncthreads();

    float isum[RD], imax[RD], jsum[RD], jmax[RD];
#pragma unroll
    for (int c = 0; c < RD; c++) { isum[c]=0.f; imax[c]=0.f; jsum[c]=0.f; jmax[c]=0.f; }

    const int s_lo = diag ? 1 : 0;
    const int s_hi = diag ? 17 : 32;
    for (int s = s_lo; s < s_hi; ++s) {
        const int jl = (lane + s) & 31;
        const bool do_bwd = !diag || (s < 16);

        u64 Aj[5], Bj[5];
#pragma unroll
        for (int t = 0; t < 5; t++) {
            Aj[t] = lds_u64(&s_aj[w][jl][2 * t]);
            Bj[t] = lds_u64(&s_bj[w][jl][2 * t]);
        }

        // symmetric part S (shared by both directions)
        u64 S0 = 0ull, S1 = 0ull, S2 = 0ull, S3 = 0ull, S4 = 0ull;
        float d2 = 0.f, qd = 0.f;
#pragma unroll
        for (int kk = 0; kk < 6; kk++) {
            float4 cj = *(const float4*)&s_cq[w][jl][4 * kk];
            float4 qj = *(const float4*)&s_cq[w][jl][24 + 4 * kk];
            const float* cjp = &cj.x;
            const float* qjp = &qj.x;
#pragma unroll
            for (int e = 0; e < 4; e++) {
                const int d = 4 * kk + e;
                float df = ci[d] - cjp[e];
                d2 = fmaf(df, df, d2);
                qd = fmaf(qi[d], qjp[e], qd);
                float ad = fabsf(df);
                u64 av = pk(ad, ad);
                u64 w0, w1v, w2v, w3v, w4v;
                lds_v2u64(w0, w1v, &s_w1[d][0]);
                lds_v2u64(w2v, w3v, &s_w1[d][4]);
                w4v = lds_u64(&s_w1[d][8]);
                S0 = f2fma(av, w0,  S0);
                S1 = f2fma(av, w1v, S1);
                S2 = f2fma(av, w2v, S2);
                S3 = f2fma(av, w3v, S3);
                S4 = f2fma(av, w4v, S4);
            }
        }
        {
            float dist = sqrtf(d2);
            u64 qp = pk(qd, qd), dp = pk(dist, dist);
            u64 wq0, wq1, wq2, wq3, wq4, wd0, wd1, wd2, wd3, wd4;
            lds_v2u64(wq0, wq1, &s_w1[24][0]);
            lds_v2u64(wq2, wq3, &s_w1[24][4]);
            wq4 = lds_u64(&s_w1[24][8]);
            lds_v2u64(wd0, wd1, &s_w1[25][0]);
            lds_v2u64(wd2, wd3, &s_w1[25][4]);
            wd4 = lds_u64(&s_w1[25][8]);
            S0 = f2fma(qp, wq0, f2fma(dp, wd0, S0));
            S1 = f2fma(qp, wq1, f2fma(dp, wd1, S1));
            S2 = f2fma(qp, wq2, f2fma(dp, wd2, S2));
            S3 = f2fma(qp, wq3, f2fma(dp, wd3, S3));
            S4 = f2fma(qp, wq4, f2fma(dp, wd4, S4));
        }

        // both directions' hidden layers
        float haf[RD], hab[RD];
        {
            u64 Sv[5] = {S0, S1, S2, S3, S4};
#pragma unroll
            for (int t = 0; t < 5; t++) {
                float lo, hi;
                u64 hf = f2add(f2add(Sv[t], Ai[t]), Bj[t]);
                upk(lo, hi, hf);
                haf[2*t]   = fmaxf(lo, 0.f);
                haf[2*t+1] = fmaxf(hi, 0.f);
                u64 hb = f2add(f2add(Sv[t], Aj[t]), Bi[t]);
                upk(lo, hi, hb);
                hab[2*t]   = fmaxf(lo, 0.f);
                hab[2*t+1] = fmaxf(hi, 0.f);
            }
        }

        // layer 2, both directions share weight loads
        u64 r2f[5], r2b[5];
#pragma unroll
        for (int t = 0; t < 5; t++) {
            u64 bb = lds_u64(&s_b2[2 * t]);
            r2f[t] = bb; r2b[t] = bb;
        }
#pragma unroll
        for (int rh = 0; rh < RD; rh++) {
            u64 w0, w1v, w2v, w3v, w4v;
            lds_v2u64(w0, w1v, &s_w2[rh][0]);
            lds_v2u64(w2v, w3v, &s_w2[rh][4]);
            w4v = lds_u64(&s_w2[rh][8]);
            u64 hhf = pk(haf[rh], haf[rh]);
            u64 hhb = pk(hab[rh], hab[rh]);
            r2f[0] = f2fma(hhf, w0,  r2f[0]);  r2b[0] = f2fma(hhb, w0,  r2b[0]);
            r2f[1] = f2fma(hhf, w1v, r2f[1]);  r2b[1] = f2fma(hhb, w1v, r2b[1]);
            r2f[2] = f2fma(hhf, w2v, r2f[2]);  r2b[2] = f2fma(hhb, w2v, r2b[2]);
            r2f[3] = f2fma(hhf, w3v, r2f[3]);  r2b[3] = f2fma(hhb, w3v, r2b[3]);
            r2f[4] = f2fma(hhf, w4v, r2f[4]);  r2b[4] = f2fma(hhb, w4v, r2b[4]);
        }

        // forward: relu + accumulate locally (row ri)
#pragma unroll
        for (int t = 0; t < 5; t++) {
            float v0, v1;
            upk(v0, v1, r2f[t]);
            v0 = fmaxf(v0, 0.f); v1 = fmaxf(v1, 0.f);
            isum[2*t]   += v0;  imax[2*t]   = fmaxf(imax[2*t],   v0);
            isum[2*t+1] += v1;  imax[2*t+1] = fmaxf(imax[2*t+1], v1);
        }
        // backward: shuffle to owner lane of row jbase+jl, then relu + acc
        if (do_bwd) {
            const int src = (lane - s) & 31;
#pragma unroll
            for (int t = 0; t < 5; t++) {
                float v0, v1;
                upk(v0, v1, r2b[t]);
                v0 = __shfl_sync(0xffffffffu, v0, src);
                v1 = __shfl_sync(0xffffffffu, v1, src);
                v0 = fmaxf(v0, 0.f); v1 = fmaxf(v1, 0.f);
                jsum[2*t]   += v0;  jmax[2*t]   = fmaxf(jmax[2*t],   v0);
                jsum[2*t+1] += v1;  jmax[2*t+1] = fmaxf(jmax[2*t+1], v1);
            }
        }
    }

    // --- write partials: slot = other tile index ---
    if (diag) {
#pragma unroll
        for (int c = 0; c < RD; c++) {
            isum[c] += jsum[c];
            imax[c] = fmaxf(imax[c], jmax[c]);
        }
    }
    {
        float* ps = &g_psum[tj][(size_t)ri * RD];
        float* pm = &g_pmax[tj][(size_t)ri * RD];
#pragma unroll
        for (int c = 0; c < RD; c++) { ps[c] = isum[c]; pm[c] = imax[c]; }
    }
    if (!diag) {
        float* ps = &g_psum[ti][(size_t)rj * RD];
        float* pm = &g_pmax[ti][(size_t)rj * RD];
#pragma unroll
        for (int c = 0; c < RD; c++) { ps[c] = jsum[c]; pm[c] = jmax[c]; }
    }
}

// ---------------------------------------------------------------------------
// Kernel 3: reduce 16 slots -> final mean / max
// ---------------------------------------------------------------------------
__global__ void reduce_kernel(float* __restrict__ out) {
    int gid = blockIdx.x * blockDim.x + threadIdx.x;
    if (gid >= ROWS * RD) return;
    float s = 0.f, m = 0.f;
#pragma unroll
    for (int o = 0; o < NT; o++) {
        s += g_psum[o][gid];
        m = fmaxf(m, g_pmax[o][gid]);
    }
    out[gid] = s * (1.0f / (float)(NSEQ - 1));
    out[ROWS * RD + gid] = m;
}

// ---------------------------------------------------------------------------
extern "C" void kernel_launch(void* const* d_in, const int* in_sizes, int n_in,
                              void* d_out, int out_size) {
    const float* x     = (const float*)d_in[0];
    const float* q     = (const float*)d_in[1];
    const float* coord = (const float*)d_in[2];
    const float* W1    = (const float*)d_in[3];
    const float* b1    = (const float*)d_in[4];
    const float* W2    = (const float*)d_in[5];
    const float* b2    = (const float*)d_in[6];
    float* out = (float*)d_out;

    precompute_kernel<<<(ROWS + 63) / 64, 64>>>(x, W1, b1);
    pair_kernel<<<(8 * NPAIRS) / 4, 128>>>(q, coord, W1, W2, b2);
    reduce_kernel<<<(ROWS * RD + 255) / 256, 256>>>(out);
}

// round 15
// speedup vs baseline: 3.1333x; 3.1333x over previous
#include <cuda_runtime.h>

#define DM 24
#define RD 10
#define NSEQ 512
#define ROWS 4096
#define APAD 12
#define CQS 52
#define JCH 128

typedef unsigned long long u64;

// Scratch (no runtime allocation allowed)
__device__ __align__(16) float g_A[ROWS * APAD];    // x@W1[0:24]+b1
__device__ __align__(16) float g_Bv[ROWS * APAD];   // x@W1[24:48]

// ---------------- f32x2 helpers ----------------
__device__ __forceinline__ u64 pk(float lo, float hi) {
    u64 r; asm("mov.b64 %0, {%1, %2};" : "=l"(r) : "f"(lo), "f"(hi)); return r;
}
__device__ __forceinline__ void upk(float& lo, float& hi, u64 v) {
    asm("mov.b64 {%0, %1}, %2;" : "=f"(lo), "=f"(hi) : "l"(v));
}
__device__ __forceinline__ u64 f2fma(u64 a, u64 b, u64 c) {
    u64 d; asm("fma.rn.f32x2 %0, %1, %2, %3;" : "=l"(d) : "l"(a), "l"(b), "l"(c)); return d;
}
__device__ __forceinline__ u64 f2add(u64 a, u64 b) {
    u64 d; asm("add.rn.f32x2 %0, %1, %2;" : "=l"(d) : "l"(a), "l"(b)); return d;
}
__device__ __forceinline__ void lds_v2u64(u64& a, u64& b, const float* p) {
    unsigned sa = (unsigned)__cvta_generic_to_shared((const void*)p);
    asm("ld.shared.v2.u64 {%0, %1}, [%2];" : "=l"(a), "=l"(b) : "r"(sa));
}
__device__ __forceinline__ u64 lds_u64(const float* p) {
    unsigned sa = (unsigned)__cvta_generic_to_shared((const void*)p);
    u64 a; asm("ld.shared.u64 %0, [%1];" : "=l"(a) : "r"(sa));
    return a;
}

// ---------------------------------------------------------------------------
// Kernel 1: precompute, 4 threads per row: (half A/B) x (r-half 0..4 / 5..9)
// ---------------------------------------------------------------------------
__global__ void precompute_kernel(const float* __restrict__ x,
                                  const float* __restrict__ W1,
                                  const float* __restrict__ b1) {
    int t = blockIdx.x * blockDim.x + threadIdx.x;
    if (t >= ROWS * 4) return;
    int row  = t >> 2;
    int sub  = t & 3;
    int half = sub >> 1;          // 0 -> A (W1 rows 0..23, +b1), 1 -> B (rows 24..47)
    int rb   = (sub & 1) * 5;     // output columns rb..rb+4

    float xv[DM];
    {
        const float4* x4 = (const float4*)(x + (size_t)row * DM);
#pragma unroll
        for (int k = 0; k < 6; k++) {
            float4 v = x4[k];
            xv[4*k] = v.x; xv[4*k+1] = v.y; xv[4*k+2] = v.z; xv[4*k+3] = v.w;
        }
    }
    const float* Wb = W1 + half * DM * RD;
    float acc[5];
#pragma unroll
    for (int r = 0; r < 5; r++) acc[r] = half ? 0.f : b1[rb + r];
#pragma unroll
    for (int d = 0; d < DM; d++) {
        float xd = xv[d];
#pragma unroll
        for (int r = 0; r < 5; r++)
            acc[r] = fmaf(xd, Wb[d * RD + rb + r], acc[r]);
    }
    float* dst = half ? g_Bv : g_A;
#pragma unroll
    for (int r = 0; r < 5; r++) dst[row * APAD + rb + r] = acc[r];
    if (rb == 5) { dst[row * APAD + 10] = 0.f; dst[row * APAD + 11] = 0.f; }
}

// ---------------------------------------------------------------------------
// Kernel 2: pairwise (R13 structure). 4 warps/block, 1 warp per i, 128-row
// staged j-chunk, 4 j's per lane. Diff/dot block packed via f32x2 using
// NEGATED ci (sign of df is irrelevant: only df^2 and |df| are used).
// ---------------------------------------------------------------------------
__global__ __launch_bounds__(128, 4)
void pair_kernel(const float* __restrict__ q,
                 const float* __restrict__ coord,
                 const float* __restrict__ W1,
                 const float* __restrict__ W2,
                 const float* __restrict__ b2,
                 float* __restrict__ out) {
    __shared__ __align__(16) float s_cq[JCH][CQS];  // [r][0:24)=coord_j, [24:48)=q_j (208B stride)
    __shared__ __align__(16) float s_bj[JCH][14];   // B_j rows (56B stride; float2/u64 access only)
    __shared__ __align__(16) float s_w1[26][12];    // [d][r]; 24=qov, 25=dist (48B rows)
    __shared__ __align__(16) float s_w2[10][12];    // [rh][c] (48B rows)
    __shared__ __align__(16) float s_ciq[4][CQS];   // per-warp: -ci (0..23), qi (24..47)
    __shared__ __align__(16) float s_ai[4][12];     // per-warp: A_i

    const int tid = threadIdx.x;
    const int w = tid >> 5, lane = tid & 31;
    const int i = blockIdx.x * 4 + w;
    const int jbase = i & ~(NSEQ - 1);

    // --- one-time fills ---
    for (int idx = tid; idx < 26 * 12; idx += 128) {
        int d = idx / 12, r = idx % 12;
        float v = 0.f;
        if (r < RD) {
            int row = (d < 24) ? (48 + d) : (d == 24 ? 72 : 73);
            v = W1[row * RD + r];
        }
        s_w1[d][r] = v;
    }
    for (int idx = tid; idx < 10 * 12; idx += 128) {
        int rh = idx / 12, c = idx % 12;
        s_w2[rh][c] = (c < RD) ? W2[rh * RD + c] : 0.f;
    }
    if (lane < DM) {
        s_ciq[w][lane]      = -coord[(size_t)i * DM + lane];   // NEGATED ci
        s_ciq[w][24 + lane] = q[(size_t)i * DM + lane];
    }
    if (lane < 12) s_ai[w][lane] = g_A[i * APAD + lane];

    u64 b2p[5];
#pragma unroll
    for (int t = 0; t < 5; t++) b2p[t] = pk(b2[2 * t], b2[2 * t + 1]);

    float sacc[RD], macc[RD];
#pragma unroll
    for (int c = 0; c < RD; c++) { sacc[c] = 0.f; macc[c] = 0.f; }

    for (int it = 0; it < NSEQ / JCH; ++it) {
        const int jb = jbase + it * JCH;
        __syncthreads();
        // --- stage 128 j-rows (coalesced) ---
        {
            const float4* gc = (const float4*)(coord + (size_t)jb * DM);
            const float4* gq = (const float4*)(q + (size_t)jb * DM);
#pragma unroll
            for (int k = tid; k < JCH * 6; k += 128) {
                int r = k / 6, c = (k % 6) * 4;
                *(float4*)&s_cq[r][c]      = gc[k];
                *(float4*)&s_cq[r][24 + c] = gq[k];
            }
            const float2* gb = (const float2*)(g_Bv + (size_t)jb * APAD);
#pragma unroll
            for (int k = tid; k < JCH * 6; k += 128) {
                int r = k / 6, c = (k % 6) * 2;
                *(float2*)&s_bj[r][c] = gb[k];
            }
        }
        __syncthreads();

        // --- per-lane: 4 pairs (i, jb + lane + 32x) ---
        u64 h2[4][5];
        u64 d2p[4], qdp[4];          // packed accumulators {even-d sum, odd-d sum}
#pragma unroll
        for (int x = 0; x < 4; x++) {
            d2p[x] = 0ull; qdp[x] = 0ull;
#pragma unroll
            for (int t = 0; t < 5; t++) {
                u64 ai = *(const u64*)&s_ai[w][2 * t];
                h2[x][t] = f2add(ai, *(const u64*)&s_bj[32 * x + lane][2 * t]);
            }
        }

#pragma unroll
        for (int kk = 0; kk < 6; ++kk) {
            float4 nci4 = *(const float4*)&s_ciq[w][4 * kk];        // -ci, broadcast
            float4 qi4  = *(const float4*)&s_ciq[w][24 + 4 * kk];
            u64 ncip[2] = { pk(nci4.x, nci4.y), pk(nci4.z, nci4.w) };
            u64 qip[2]  = { pk(qi4.x,  qi4.y),  pk(qi4.z,  qi4.w)  };
            float4 cj[4], qj[4];
#pragma unroll
            for (int x = 0; x < 4; x++) {
                cj[x] = *(const float4*)&s_cq[32 * x + lane][4 * kk];
                qj[x] = *(const float4*)&s_cq[32 * x + lane][24 + 4 * kk];
            }
#pragma unroll
            for (int ep = 0; ep < 2; ep++) {                 // d-pair within this kk
                const int d = 4 * kk + 2 * ep;
                u64 av0[4], av1[4];
#pragma unroll
                for (int x = 0; x < 4; x++) {
                    u64 cjp = ep ? pk(cj[x].z, cj[x].w) : pk(cj[x].x, cj[x].y);
                    u64 qjp = ep ? pk(qj[x].z, qj[x].w) : pk(qj[x].x, qj[x].y);
                    u64 mdfp = f2add(ncip[ep], cjp);          // {-df_d, -df_d1}
                    d2p[x] = f2fma(mdfp, mdfp, d2p[x]);
                    qdp[x] = f2fma(qip[ep], qjp, qdp[x]);
                    float m0, m1;
                    upk(m0, m1, mdfp);                        // reg alias, no movs
                    float a0 = fabsf(m0), a1 = fabsf(m1);
                    av0[x] = pk(a0, a0);
                    av1[x] = pk(a1, a1);
                }
                // weights for d and d+1
                u64 wA0, wA1, wA2, wA3, wA4;
                lds_v2u64(wA0, wA1, &s_w1[d][0]);
                lds_v2u64(wA2, wA3, &s_w1[d][4]);
                wA4 = lds_u64(&s_w1[d][8]);
                u64 wB0, wB1, wB2, wB3, wB4;
                lds_v2u64(wB0, wB1, &s_w1[d + 1][0]);
                lds_v2u64(wB2, wB3, &s_w1[d + 1][4]);
                wB4 = lds_u64(&s_w1[d + 1][8]);
#pragma unroll
                for (int x = 0; x < 4; x++) {
                    h2[x][0] = f2fma(av0[x], wA0, h2[x][0]);
                    h2[x][1] = f2fma(av0[x], wA1, h2[x][1]);
                    h2[x][2] = f2fma(av0[x], wA2, h2[x][2]);
                    h2[x][3] = f2fma(av0[x], wA3, h2[x][3]);
                    h2[x][4] = f2fma(av0[x], wA4, h2[x][4]);
                    h2[x][0] = f2fma(av1[x], wB0, h2[x][0]);
                    h2[x][1] = f2fma(av1[x], wB1, h2[x][1]);
                    h2[x][2] = f2fma(av1[x], wB2, h2[x][2]);
                    h2[x][3] = f2fma(av1[x], wB3, h2[x][3]);
                    h2[x][4] = f2fma(av1[x], wB4, h2[x][4]);
                }
            }
        }
        // horizontal finish of packed d2/qd, then tail features
        u64 qp[4], dp[4];
#pragma unroll
        for (int x = 0; x < 4; x++) {
            float de, do_, qe, qo;
            upk(de, do_, d2p[x]);
            upk(qe, qo, qdp[x]);
            float ds = sqrtf(de + do_);
            float qd = qe + qo;
            qp[x] = pk(qd, qd);
            dp[x] = pk(ds, ds);
        }
        {
            u64 wq0, wq1, wq2, wq3, wq4, wd0, wd1, wd2, wd3, wd4;
            lds_v2u64(wq0, wq1, &s_w1[24][0]);
            lds_v2u64(wq2, wq3, &s_w1[24][4]);
            wq4 = lds_u64(&s_w1[24][8]);
            lds_v2u64(wd0, wd1, &s_w1[25][0]);
            lds_v2u64(wd2, wd3, &s_w1[25][4]);
            wd4 = lds_u64(&s_w1[25][8]);
#pragma unroll
            for (int x = 0; x < 4; x++) {
                h2[x][0] = f2fma(qp[x], wq0, h2[x][0]); h2[x][0] = f2fma(dp[x], wd0, h2[x][0]);
                h2[x][1] = f2fma(qp[x], wq1, h2[x][1]); h2[x][1] = f2fma(dp[x], wd1, h2[x][1]);
                h2[x][2] = f2fma(qp[x], wq2, h2[x][2]); h2[x][2] = f2fma(dp[x], wd2, h2[x][2]);
                h2[x][3] = f2fma(qp[x], wq3, h2[x][3]); h2[x][3] = f2fma(dp[x], wd3, h2[x][3]);
                h2[x][4] = f2fma(qp[x], wq4, h2[x][4]); h2[x][4] = f2fma(dp[x], wd4, h2[x][4]);
            }
        }
        // relu -> hidden scalars
        float ha[4][RD];
#pragma unroll
        for (int x = 0; x < 4; x++) {
#pragma unroll
            for (int t = 0; t < 5; t++) {
                float lo, hi;
                upk(lo, hi, h2[x][t]);
                ha[x][2 * t]     = fmaxf(lo, 0.f);
                ha[x][2 * t + 1] = fmaxf(hi, 0.f);
            }
        }

        // layer 2: each weight load feeds 4 pairs
        u64 r2[4][5];
#pragma unroll
        for (int x = 0; x < 4; x++)
#pragma unroll
            for (int t = 0; t < 5; t++) r2[x][t] = b2p[t];
#pragma unroll
        for (int rh = 0; rh < RD; rh++) {
            u64 hh[4];
#pragma unroll
            for (int x = 0; x < 4; x++) hh[x] = pk(ha[x][rh], ha[x][rh]);
            u64 w0, w1v, w2v, w3v, w4v;
            lds_v2u64(w0, w1v, &s_w2[rh][0]);
            lds_v2u64(w2v, w3v, &s_w2[rh][4]);
            w4v = lds_u64(&s_w2[rh][8]);
#pragma unroll
            for (int x = 0; x < 4; x++) {
                r2[x][0] = f2fma(hh[x], w0,  r2[x][0]);
                r2[x][1] = f2fma(hh[x], w1v, r2[x][1]);
                r2[x][2] = f2fma(hh[x], w2v, r2[x][2]);
                r2[x][3] = f2fma(hh[x], w3v, r2[x][3]);
                r2[x][4] = f2fma(hh[x], w4v, r2[x][4]);
            }
        }
        // relu + masked accumulate
#pragma unroll
        for (int x = 0; x < 4; x++) {
            const bool off = (jb + 32 * x + lane) != i;
            if (off) {
#pragma unroll
                for (int t = 0; t < 5; t++) {
                    float r0, r1;
                    upk(r0, r1, r2[x][t]);
                    r0 = fmaxf(r0, 0.f); r1 = fmaxf(r1, 0.f);
                    sacc[2 * t]     += r0;  macc[2 * t]     = fmaxf(macc[2 * t], r0);
                    sacc[2 * t + 1] += r1;  macc[2 * t + 1] = fmaxf(macc[2 * t + 1], r1);
                }
            }
        }
    }

    // warp reduction across j-lanes (deterministic tree)
#pragma unroll
    for (int c = 0; c < RD; c++) {
#pragma unroll
        for (int o = 16; o > 0; o >>= 1) {
            sacc[c] += __shfl_xor_sync(0xffffffffu, sacc[c], o);
            macc[c] = fmaxf(macc[c], __shfl_xor_sync(0xffffffffu, macc[c], o));
        }
    }
    if (lane == 0) {
        const float inv = 1.0f / (float)(NSEQ - 1);
#pragma unroll
        for (int c = 0; c < RD; c++) {
            out[(size_t)i * RD + c] = sacc[c] * inv;
            out[(size_t)ROWS * RD + (size_t)i * RD + c] = macc[c];
        }
    }
}

// ---------------------------------------------------------------------------
extern "C" void kernel_launch(void* const* d_in, const int* in_sizes, int n_in,
                              void* d_out, int out_size) {
    const float* x     = (const float*)d_in[0];
    const float* q     = (const float*)d_in[1];
    const float* coord = (const float*)d_in[2];
    const float* W1    = (const float*)d_in[3];
    const float* b1    = (const float*)d_in[4];
    const float* W2    = (const float*)d_in[5];
    const float* b2    = (const float*)d_in[6];
    float* out = (float*)d_out;

    precompute_kernel<<<(ROWS * 4 + 127) / 128, 128>>>(x, W1, b1);
    pair_kernel<<<ROWS / 4, 128>>>(q, coord, W1, W2, b2, out);
}